// round 6
// baseline (speedup 1.0000x reference)
#include <cuda_runtime.h>
#include <math.h>

#define RD      2048
#define RE      8
#define RNE     16            // gate(8) + noise(8) expert rows in smem
#define RNTOK   16384         // B*S
#define TPB     448           // 14 warps
#define NWARPS  14
#define NBLK    148
#define TOKW    8             // tokens per warp job
#define TOTAL_JOBS (RNTOK/TOKW)   // 2048 jobs; 148*14=2072 warps -> 1 job/warp
#define WSTRIDE (NBLK*NWARPS)
#define NCHUNK  (RD/32)       // 64 chunks of 32 d
#define PROBS_ELEMS (RNTOK*RE)

// packed 2xfp32 FMA (Blackwell) — 2x fp32 throughput vs 3-reg FFMA
__device__ __forceinline__ void ffma2(unsigned long long& d,
                                      unsigned long long a,
                                      unsigned long long b) {
    asm("fma.rn.f32x2 %0, %1, %2, %0;" : "+l"(d) : "l"(a), "l"(b));
}
__device__ __forceinline__ float lo32(unsigned long long v) {
    return __uint_as_float((unsigned)(v & 0xffffffffull));
}
__device__ __forceinline__ float hi32(unsigned long long v) {
    return __uint_as_float((unsigned)(v >> 32));
}

__global__ void __launch_bounds__(TPB, 1) router_kernel(
    const float* __restrict__ x,
    const float* __restrict__ gate_w,
    const float* __restrict__ gate_b,
    const float* __restrict__ noise_w,
    const float* __restrict__ noise_b,
    const float* __restrict__ noise,
    float* __restrict__ out, int out_size)
{
    // Weights expert-major in smem: sw[e][d], e<8 gate, e>=8 noise. 128 KB.
    extern __shared__ float sw[];
    for (int i = threadIdx.x; i < RD * RE; i += TPB) {
        int d = i >> 3, e = i & 7;           // gate_w/noise_w are [D, E] row-major
        sw[e * RD + d]       = gate_w[i];
        sw[(e + 8) * RD + d] = noise_w[i];
    }
    __syncthreads();

    const int lane  = threadIdx.x & 31;
    const int warp  = threadIdx.x >> 5;
    const int gwarp = blockIdx.x * NWARPS + warp;
    const int dsub  = lane & 7;    // d position within chunk (4 floats each)
    const int egrp  = lane >> 3;   // expert group: rows egrp*4 .. egrp*4+3

    const float* wp = sw + (egrp * 4) * RD + dsub * 4;

    for (int job = gwarp; job < TOTAL_JOBS; job += WSTRIDE) {
        const int t0 = job * TOKW;

        unsigned long long acc2[TOKW][4];    // [token][expert-in-group], d-pair packed
        #pragma unroll
        for (int t = 0; t < TOKW; ++t)
            #pragma unroll
            for (int k = 0; k < 4; ++k) acc2[t][k] = 0ull;

        const float* xp = x + (size_t)t0 * RD + dsub * 4;
        const float* wq = wp;

        #pragma unroll 2
        for (int s = 0; s < NCHUNK; ++s) {
            // x for 8 tokens at this chunk; pointer-incremented addressing so
            // ptxas can hoist next-iter LDGs into the ffma shadow under unroll
            ulonglong2 xv[TOKW];
            #pragma unroll
            for (int t = 0; t < TOKW; ++t)
                xv[t] = *reinterpret_cast<const ulonglong2*>(xp + (size_t)t * RD);

            // 4 conflict-free LDS.128: this lane's 4 experts at its 4 d
            ulonglong2 wv[4];
            #pragma unroll
            for (int k = 0; k < 4; ++k)
                wv[k] = *reinterpret_cast<const ulonglong2*>(wq + k * RD);

            #pragma unroll
            for (int t = 0; t < TOKW; ++t)
                #pragma unroll
                for (int k = 0; k < 4; ++k) {
                    ffma2(acc2[t][k], xv[t].x, wv[k].x);
                    ffma2(acc2[t][k], xv[t].y, wv[k].y);
                }

            xp += 32;
            wq += 32;
        }

        // collapse d-pair halves
        float accf[TOKW][4];
        #pragma unroll
        for (int t = 0; t < TOKW; ++t)
            #pragma unroll
            for (int k = 0; k < 4; ++k)
                accf[t][k] = lo32(acc2[t][k]) + hi32(acc2[t][k]);

        // reduce over dsub (lane bits 0..2): full sums per egrp at every lane
        #pragma unroll
        for (int m = 1; m <= 4; m <<= 1)
            #pragma unroll
            for (int t = 0; t < TOKW; ++t)
                #pragma unroll
                for (int k = 0; k < 4; ++k)
                    accf[t][k] += __shfl_xor_sync(0xffffffffu, accf[t][k], m);

        // gather 16 experts to lanes 0..7 (lane t finalizes token t0+t)
        float my[16];
        #pragma unroll
        for (int t = 0; t < TOKW; ++t)
            #pragma unroll
            for (int g = 0; g < 4; ++g)
                #pragma unroll
                for (int k = 0; k < 4; ++k) {
                    float v = __shfl_sync(0xffffffffu, accf[t][k], g * 8);
                    if (lane == t) my[g * 4 + k] = v;
                }

        if (lane < TOKW) {
            const int tok = t0 + lane;
            float noisy[8];
            #pragma unroll
            for (int e = 0; e < 8; ++e) {
                float lg = my[e]     + gate_b[e];
                float z  = my[e + 8] + noise_b[e];
                float sp = fmaxf(z, 0.f) + log1pf(expf(-fabsf(z)));   // softplus
                noisy[e] = lg + noise[(size_t)tok * 8 + e] * sp;
            }

            // top-2, tie-break toward lower index (matches lax.top_k)
            float v0 = -INFINITY, v1 = -INFINITY;
            int   i0 = 0,         i1 = 0;
            #pragma unroll
            for (int e = 0; e < 8; ++e) {
                float v = noisy[e];
                if (v > v0)      { v1 = v0; i1 = i0; v0 = v; i0 = e; }
                else if (v > v1) { v1 = v;  i1 = e; }
            }

            float e1  = expf(v1 - v0);
            float inv = 1.f / (1.f + e1);
            float p0 = inv, p1 = e1 * inv;

            float pv[8];
            #pragma unroll
            for (int e = 0; e < 8; ++e)
                pv[e] = (e == i0) ? p0 : ((e == i1) ? p1 : 0.f);

            float4* po = reinterpret_cast<float4*>(out + (size_t)tok * 8);
            po[0] = make_float4(pv[0], pv[1], pv[2], pv[3]);
            po[1] = make_float4(pv[4], pv[5], pv[6], pv[7]);

            const int ib = PROBS_ELEMS + tok * 2;
            if (ib + 1 < out_size) {
                out[ib]     = (float)i0;
                out[ib + 1] = (float)i1;
            }
        }
    }
}

extern "C" void kernel_launch(void* const* d_in, const int* in_sizes, int n_in,
                              void* d_out, int out_size) {
    const float* x       = (const float*)d_in[0];
    const float* gate_w  = (const float*)d_in[1];
    const float* gate_b  = (const float*)d_in[2];
    const float* noise_w = (const float*)d_in[3];
    const float* noise_b = (const float*)d_in[4];
    const float* noise   = (const float*)d_in[5];
    // d_in[6] = top_k (fixed = 2, baked in)

    const size_t smem = (size_t)RNE * RD * sizeof(float);   // 128 KB
    cudaFuncSetAttribute(router_kernel,
                         cudaFuncAttributeMaxDynamicSharedMemorySize, (int)smem);
    router_kernel<<<NBLK, TPB, smem>>>(x, gate_w, gate_b, noise_w, noise_b,
                                       noise, (float*)d_out, out_size);
}

// round 7
// speedup vs baseline: 1.0263x; 1.0263x over previous
#include <cuda_runtime.h>
#include <math.h>

#define RD      2048
#define RE      8
#define RNE     16            // gate(8) + noise(8) expert rows in smem
#define RNTOK   16384         // B*S
#define TPB     512           // 16 warps
#define NWARPS  16
#define NBLK    148
#define TOKW    8             // tokens per warp job
#define TOTAL_JOBS (RNTOK/TOKW)   // 2048
#define NCHUNK  (RD/32)       // 64 chunks of 32 d
#define PROBS_ELEMS (RNTOK*RE)

// packed 2xfp32 FMA (Blackwell) — 2x fp32 throughput vs 3-reg FFMA
__device__ __forceinline__ void ffma2(unsigned long long& d,
                                      unsigned long long a,
                                      unsigned long long b) {
    asm("fma.rn.f32x2 %0, %1, %2, %0;" : "+l"(d) : "l"(a), "l"(b));
}
__device__ __forceinline__ float lo32(unsigned long long v) {
    return __uint_as_float((unsigned)(v & 0xffffffffull));
}
__device__ __forceinline__ float hi32(unsigned long long v) {
    return __uint_as_float((unsigned)(v >> 32));
}

__global__ void __launch_bounds__(TPB, 1) router_kernel(
    const float* __restrict__ x,
    const float* __restrict__ gate_w,
    const float* __restrict__ gate_b,
    const float* __restrict__ noise_w,
    const float* __restrict__ noise_b,
    const float* __restrict__ noise,
    float* __restrict__ out, int out_size)
{
    // Weights expert-major in smem: sw[e][d], e<8 gate, e>=8 noise. 128 KB.
    extern __shared__ float sw[];
    for (int i = threadIdx.x; i < RD * RE; i += TPB) {
        int d = i >> 3, e = i & 7;           // gate_w/noise_w are [D, E] row-major
        sw[e * RD + d]       = gate_w[i];
        sw[(e + 8) * RD + d] = noise_w[i];
    }
    __syncthreads();

    const int lane = threadIdx.x & 31;
    const int warp = threadIdx.x >> 5;
    // balanced mapping: every SM gets 13-14 busy warps
    const int job  = warp * NBLK + blockIdx.x;
    if (job >= TOTAL_JOBS) return;

    const int dsub = lane & 7;    // d position within chunk (4 floats each)
    const int egrp = lane >> 3;   // expert group: rows egrp*4 .. egrp*4+3

    const float* wq = sw + (egrp * 4) * RD + dsub * 4;
    const int t0 = job * TOKW;
    const float* xp = x + (size_t)t0 * RD + dsub * 4;

    unsigned long long acc2[TOKW][4];    // [token][expert-in-group], d-pair packed
    #pragma unroll
    for (int t = 0; t < TOKW; ++t)
        #pragma unroll
        for (int k = 0; k < 4; ++k) acc2[t][k] = 0ull;

    // prime double-buffer for tokens 0-3, chunk 0
    ulonglong2 xv[4];
    #pragma unroll
    for (int t = 0; t < 4; ++t)
        xv[t] = *reinterpret_cast<const ulonglong2*>(xp + (size_t)t * RD);

    #pragma unroll 1
    for (int s = 0; s < NCHUNK; ++s) {
        const float* xcur = xp + s * 32;
        // wrap on last iter: dead value, always-valid address
        const float* xnxt = xp + (((s + 1) & (NCHUNK - 1)) * 32);

        // front-batched LDGs (MLP=8):
        // xc: tokens 4-7 of CURRENT chunk (consumed after ~40 instrs)
        ulonglong2 xc[4];
        #pragma unroll
        for (int t = 0; t < 4; ++t)
            xc[t] = *reinterpret_cast<const ulonglong2*>(xcur + (size_t)(t + 4) * RD);
        // xn: tokens 0-3 of NEXT chunk (full-iteration lookahead)
        ulonglong2 xn[4];
        #pragma unroll
        for (int t = 0; t < 4; ++t)
            xn[t] = *reinterpret_cast<const ulonglong2*>(xnxt + (size_t)t * RD);

        // 4 conflict-free LDS.128: this lane's 4 experts at its 4 d
        ulonglong2 wv[4];
        const float* wps = wq + s * 32;
        #pragma unroll
        for (int k = 0; k < 4; ++k)
            wv[k] = *reinterpret_cast<const ulonglong2*>(wps + k * RD);

        // tokens 0-3 first (xv ready since last iter)
        #pragma unroll
        for (int t = 0; t < 4; ++t)
            #pragma unroll
            for (int k = 0; k < 4; ++k) {
                ffma2(acc2[t][k], xv[t].x, wv[k].x);
                ffma2(acc2[t][k], xv[t].y, wv[k].y);
            }
        // tokens 4-7 (xc had ~40-instr shadow)
        #pragma unroll
        for (int t = 0; t < 4; ++t)
            #pragma unroll
            for (int k = 0; k < 4; ++k) {
                ffma2(acc2[t + 4][k], xc[t].x, wv[k].x);
                ffma2(acc2[t + 4][k], xc[t].y, wv[k].y);
            }

        #pragma unroll
        for (int t = 0; t < 4; ++t) xv[t] = xn[t];
    }

    // collapse d-pair halves
    float accf[TOKW][4];
    #pragma unroll
    for (int t = 0; t < TOKW; ++t)
        #pragma unroll
        for (int k = 0; k < 4; ++k)
            accf[t][k] = lo32(acc2[t][k]) + hi32(acc2[t][k]);

    // reduce over dsub (lane bits 0..2): full sums per egrp at every lane
    #pragma unroll
    for (int m = 1; m <= 4; m <<= 1)
        #pragma unroll
        for (int t = 0; t < TOKW; ++t)
            #pragma unroll
            for (int k = 0; k < 4; ++k)
                accf[t][k] += __shfl_xor_sync(0xffffffffu, accf[t][k], m);

    // gather 16 experts to lanes 0..7 (lane t finalizes token t0+t)
    float my[16];
    #pragma unroll
    for (int t = 0; t < TOKW; ++t)
        #pragma unroll
        for (int g = 0; g < 4; ++g)
            #pragma unroll
            for (int k = 0; k < 4; ++k) {
                float v = __shfl_sync(0xffffffffu, accf[t][k], g * 8);
                if (lane == t) my[g * 4 + k] = v;
            }

    if (lane < TOKW) {
        const int tok = t0 + lane;
        float noisy[8];
        #pragma unroll
        for (int e = 0; e < 8; ++e) {
            float lg = my[e]     + gate_b[e];
            float z  = my[e + 8] + noise_b[e];
            float sp = fmaxf(z, 0.f) + log1pf(expf(-fabsf(z)));   // softplus
            noisy[e] = lg + noise[(size_t)tok * 8 + e] * sp;
        }

        // top-2, tie-break toward lower index (matches lax.top_k)
        float v0 = -INFINITY, v1 = -INFINITY;
        int   i0 = 0,         i1 = 0;
        #pragma unroll
        for (int e = 0; e < 8; ++e) {
            float v = noisy[e];
            if (v > v0)      { v1 = v0; i1 = i0; v0 = v; i0 = e; }
            else if (v > v1) { v1 = v;  i1 = e; }
        }

        float e1  = expf(v1 - v0);
        float inv = 1.f / (1.f + e1);
        float p0 = inv, p1 = e1 * inv;

        float pv[8];
        #pragma unroll
        for (int e = 0; e < 8; ++e)
            pv[e] = (e == i0) ? p0 : ((e == i1) ? p1 : 0.f);

        float4* po = reinterpret_cast<float4*>(out + (size_t)tok * 8);
        po[0] = make_float4(pv[0], pv[1], pv[2], pv[3]);
        po[1] = make_float4(pv[4], pv[5], pv[6], pv[7]);

        const int ib = PROBS_ELEMS + tok * 2;
        if (ib + 1 < out_size) {
            out[ib]     = (float)i0;
            out[ib + 1] = (float)i1;
        }
    }
}

extern "C" void kernel_launch(void* const* d_in, const int* in_sizes, int n_in,
                              void* d_out, int out_size) {
    const float* x       = (const float*)d_in[0];
    const float* gate_w  = (const float*)d_in[1];
    const float* gate_b  = (const float*)d_in[2];
    const float* noise_w = (const float*)d_in[3];
    const float* noise_b = (const float*)d_in[4];
    const float* noise   = (const float*)d_in[5];
    // d_in[6] = top_k (fixed = 2, baked in)

    const size_t smem = (size_t)RNE * RD * sizeof(float);   // 128 KB
    cudaFuncSetAttribute(router_kernel,
                         cudaFuncAttributeMaxDynamicSharedMemorySize, (int)smem);
    router_kernel<<<NBLK, TPB, smem>>>(x, gate_w, gate_b, noise_w, noise_b,
                                       noise, (float*)d_out, out_size);
}